// round 15
// baseline (speedup 1.0000x reference)
#include <cuda_runtime.h>
#include <cuda_bf16.h>
#include <math.h>
#include <cstdint>

#define BB 8
#define CC 256
#define CI 128
#define HH 64
#define WWID 64
#define NN 4096
#define NK 1024

typedef unsigned long long u64;

// ---------------- packed fp32x2 helpers (FFMA2) ----------------
__device__ __forceinline__ u64 pk2(float lo, float hi) {
    u64 r; asm("mov.b64 %0, {%1, %2};" : "=l"(r) : "f"(lo), "f"(hi)); return r;
}
__device__ __forceinline__ u64 dup2(float v) { return pk2(v, v); }
__device__ __forceinline__ void up2(float& lo, float& hi, u64 v) {
    asm("mov.b64 {%0, %1}, %2;" : "=f"(lo), "=f"(hi) : "l"(v));
}
__device__ __forceinline__ void fma2(u64& d, u64 a, u64 b) {
    asm("fma.rn.f32x2 %0, %1, %2, %0;" : "+l"(d) : "l"(a), "l"(b));
}

// ---------------- warp-MMA / async-copy helpers (sm_80-era PTX) ----------------
__device__ __forceinline__ uint32_t smem_u32(const void* p) {
    uint32_t a;
    asm("{ .reg .u64 t; cvta.to.shared.u64 t, %1; cvt.u32.u64 %0, t; }" : "=r"(a) : "l"(p));
    return a;
}
#define CVT_BF16X2(res, a, b) \
    asm("cvt.rn.satfinite.bf16x2.f32 %0, %1, %2;" : "=r"(res) : "f"(b), "f"(a))

__device__ __forceinline__ void ldsm_x4(uint32_t& a0, uint32_t& a1, uint32_t& a2,
                                        uint32_t& a3, uint32_t addr) {
    asm volatile("ldmatrix.sync.aligned.m8n8.x4.shared.b16 {%0,%1,%2,%3}, [%4];"
                 : "=r"(a0), "=r"(a1), "=r"(a2), "=r"(a3) : "r"(addr));
}
__device__ __forceinline__ void mma_bf16(float* c, uint32_t a0, uint32_t a1,
                                         uint32_t a2, uint32_t a3,
                                         uint32_t b0, uint32_t b1) {
    asm volatile("mma.sync.aligned.m16n8k16.row.col.f32.bf16.bf16.f32 "
                 "{%0,%1,%2,%3}, {%4,%5,%6,%7}, {%8,%9}, {%0,%1,%2,%3};"
                 : "+f"(c[0]), "+f"(c[1]), "+f"(c[2]), "+f"(c[3])
                 : "r"(a0), "r"(a1), "r"(a2), "r"(a3), "r"(b0), "r"(b1));
}
__device__ __forceinline__ void cp_async16(uint32_t s, const void* g) {
    asm volatile("cp.async.ca.shared.global [%0], [%1], 16;" :: "r"(s), "l"(g));
}
#define CP_COMMIT() asm volatile("cp.async.commit_group;" ::: "memory")
#define CP_WAIT(n)  asm volatile("cp.async.wait_group %0;" :: "n"(n) : "memory")

// split helpers (fp32 -> bf16 hi + bf16 residue lo)
__device__ __forceinline__ void split4(const float* v, uint2& h, uint2& l) {
    float h0 = __bfloat162float(__float2bfloat16(v[0]));
    float h1 = __bfloat162float(__float2bfloat16(v[1]));
    float h2 = __bfloat162float(__float2bfloat16(v[2]));
    float h3 = __bfloat162float(__float2bfloat16(v[3]));
    CVT_BF16X2(h.x, v[0], v[1]);
    CVT_BF16X2(h.y, v[2], v[3]);
    CVT_BF16X2(l.x, v[0] - h0, v[1] - h1);
    CVT_BF16X2(l.y, v[2] - h2, v[3] - h3);
}
__device__ __forceinline__ void split2(float a, float b, uint32_t& h, uint32_t& l) {
    float ha = __bfloat162float(__float2bfloat16(a));
    float hb = __bfloat162float(__float2bfloat16(b));
    CVT_BF16X2(h, a, b);
    CVT_BF16X2(l, a - ha, b - hb);
}
__device__ __forceinline__ float qmax(float v) {
    v = fmaxf(v, __shfl_xor_sync(0xffffffffu, v, 4));
    v = fmaxf(v, __shfl_xor_sync(0xffffffffu, v, 8));
    return v;
}

// ---------------- scratch (device globals) ----------------
__device__ __align__(16) float d_y[BB * NN * CI];             // [B][N][CI]
__device__ __align__(16) float d_wT[CI * CC];
__device__ __align__(16) __nv_bfloat16 d_thh[BB * NN * CI];   // theta [B][N][CI]
__device__ __align__(16) __nv_bfloat16 d_thl[BB * NN * CI];
__device__ __align__(16) __nv_bfloat16 d_phh[BB * NK * CI];   // phi   [B][Nk][CI]
__device__ __align__(16) __nv_bfloat16 d_phl[BB * NK * CI];
__device__ __align__(16) __nv_bfloat16 d_gh[BB * CI * NK];    // g     [B][CI][Nk]
__device__ __align__(16) __nv_bfloat16 d_gl[BB * CI * NK];
__device__ __align__(16) __nv_bfloat16 d_xh[BB * NN * CC];    // xT    [B][n_perm][C]
__device__ __align__(16) __nv_bfloat16 d_xl[BB * NN * CC];
__device__ __align__(16) __nv_bfloat16 d_wsh[3 * CI * CC];    // w     [z][CI][C]
__device__ __align__(16) __nv_bfloat16 d_wsl[3 * CI * CC];

// =====================================================================
// Kernel 0a: transpose W_w -> d_wT (for wz)
// =====================================================================
__global__ void wt_kernel(const float* __restrict__ Ww)
{
    int idx = blockIdx.x * 256 + threadIdx.x;
    if (idx < CC * (CI / 4)) {
        int c  = idx >> 5;
        int g4 = idx & 31;
        float4 v = ((const float4*)Ww)[idx];
        int ci = g4 * 4;
        d_wT[(ci + 0) * CC + c] = v.x;
        d_wT[(ci + 1) * CC + c] = v.y;
        d_wT[(ci + 2) * CC + c] = v.z;
        d_wT[(ci + 3) * CC + c] = v.w;
    }
}

// =====================================================================
// Kernel 0b: split projection weights -> bf16 hi/lo.  z: 0=theta,1=phi,2=g
// =====================================================================
__global__ void wsplit_kernel(const float* __restrict__ th_w,
                              const float* __restrict__ ph_w,
                              const float* __restrict__ g_w)
{
    const int PER = CI * CC / 4;   // 8192 float4 per matrix
    int idx = blockIdx.x * 256 + threadIdx.x;
    if (idx >= 3 * PER) return;
    int z = idx / PER, off = idx - z * PER;
    const float* src = (z == 0) ? th_w : (z == 1) ? ph_w : g_w;
    float v[4];
    *(float4*)v = ((const float4*)src)[off];
    uint2 h, l;
    split4(v, h, l);
    ((uint2*)(d_wsh + (size_t)z * CI * CC))[off] = h;
    ((uint2*)(d_wsl + (size_t)z * CI * CC))[off] = l;
}

// =====================================================================
// Kernel 0c: split_x — fuse [B][C][N] -> xT bf16 hi/lo [B][n_perm][C].
// grid (32 rowpairs, 4 c-chunks, B), block 256.
// =====================================================================
__global__ __launch_bounds__(256, 2)
void splitx_kernel(const float* __restrict__ x)
{
    __shared__ float tile[64 * 132];   // [c][perm]
    const int r  = blockIdx.x;
    const int c0 = blockIdx.y * 64;
    const int b  = blockIdx.z;
    const int tid = threadIdx.x;

    const float* xb = x + ((size_t)b * CC + c0) * NN + (2 * r) * WWID;
#pragma unroll
    for (int it = 0; it < 8; it++) {
        int id = it * 256 + tid;
        int c = id >> 5, n4 = id & 31;
        float4 v = *(const float4*)&xb[(size_t)c * NN + ((n4 * 4) >> 6) * WWID + ((n4 * 4) & 63)];
        int row = (n4 * 4) >> 6;
#pragma unroll
        for (int e = 0; e < 4; e++) {
            int wcol = (n4 * 4 + e) & 63;
            int perm = ((wcol >> 1) << 2) | (row << 1) | (wcol & 1);
            tile[c * 132 + perm] = ((const float*)&v)[e];
        }
    }
    __syncthreads();

    __nv_bfloat16* oh = d_xh + ((size_t)b * NN + r * 128) * CC + c0;
    __nv_bfloat16* ol = d_xl + ((size_t)b * NN + r * 128) * CC + c0;
#pragma unroll
    for (int it = 0; it < 8; it++) {
        int id = it * 256 + tid;
        int p = id >> 4, cq = (id & 15) * 4;
        float v[4];
        v[0] = tile[(cq + 0) * 132 + p];
        v[1] = tile[(cq + 1) * 132 + p];
        v[2] = tile[(cq + 2) * 132 + p];
        v[3] = tile[(cq + 3) * 132 + p];
        uint2 h, l;
        split4(v, h, l);
        *(uint2*)(oh + (size_t)p * CC + cq) = h;
        *(uint2*)(ol + (size_t)p * CC + cq) = l;
    }
}

// =====================================================================
// Kernel 0d: dedicated lc/gc band copy (float4 grid-stride, high MLP).
// =====================================================================
__global__ void copy_kernel(const float4* __restrict__ lc,
                            const float4* __restrict__ gc,
                            float4* __restrict__ out)
{
    const size_t PER_B = 262144;   // float4 per (batch, 256ch, 4096px)
    const size_t TOT   = BB * PER_B;
    const size_t OUT_B = 786432;
    const size_t stride = (size_t)gridDim.x * blockDim.x;
    for (size_t i = (size_t)blockIdx.x * blockDim.x + threadIdx.x;
         i < TOT; i += stride) {
        size_t bidx = i / PER_B, rem = i % PER_B;
        out[bidx * OUT_B + rem]             = lc[i];
        out[bidx * OUT_B + 2 * PER_B + rem] = gc[i];
    }
}

// =====================================================================
// Kernel 1: tensor-core projections (copy un-folded).
// grid (32 rowpairs, B, 3 proj), block 256 (8 warps x 16 px rows).
// =====================================================================
#define PJ_AH 0
#define PJ_AL 18432
#define PJ_BH 36864
#define PJ_BL 55296
#define PJ_BUF 73728
#define PROJ_SMEM_BYTES (2 * PJ_BUF)

__device__ __forceinline__ void pj_prefetch(uint32_t bufb,
                                            const __nv_bfloat16* xh,
                                            const __nv_bfloat16* xl,
                                            const __nv_bfloat16* wh,
                                            const __nv_bfloat16* wl,
                                            int k0, int tid)
{
#pragma unroll
    for (int it = 0; it < 4; it++) {
        int idx = it * 256 + tid;              // 0..1023
        int row = idx >> 3, c8 = (idx & 7) * 8;
        uint32_t so = row * 144 + c8 * 2;
        cp_async16(bufb + PJ_AH + so, xh + (size_t)row * CC + k0 + c8);
        cp_async16(bufb + PJ_AL + so, xl + (size_t)row * CC + k0 + c8);
        cp_async16(bufb + PJ_BH + so, wh + (size_t)row * CC + k0 + c8);
        cp_async16(bufb + PJ_BL + so, wl + (size_t)row * CC + k0 + c8);
    }
}

__global__ __launch_bounds__(256, 1)
void proj_mma_kernel(const float* __restrict__ g_b,
                     const float* __restrict__ th_b,
                     const float* __restrict__ ph_b)
{
    extern __shared__ char smc[];
    const uint32_t sb = smem_u32(smc);
    const int r    = blockIdx.x;
    const int b    = blockIdx.y;
    const int z    = blockIdx.z;   // 0 theta, 1 phi, 2 g
    const int tid  = threadIdx.x;
    const int wid  = tid >> 5;
    const int lane = tid & 31;

    const __nv_bfloat16* xh = d_xh + ((size_t)b * NN + r * 128) * CC;
    const __nv_bfloat16* xl = d_xl + ((size_t)b * NN + r * 128) * CC;
    const __nv_bfloat16* wh = d_wsh + (size_t)z * CI * CC;
    const __nv_bfloat16* wl = d_wsl + (size_t)z * CI * CC;
    const float* bias = (z == 0) ? th_b : (z == 1) ? ph_b : g_b;

    pj_prefetch(sb, xh, xl, wh, wl, 0, tid);
    CP_COMMIT();

    const int a_row = (lane & 7) + 8 * ((lane >> 3) & 1);
    const int a_col = 8 * (lane >> 4);
    const int b4_row = 8 * (lane >> 4) + (lane & 7);
    const int b4_col = 8 * ((lane >> 3) & 1);
    const int Rbase = wid * 16;

    float cacc[16][4];
#pragma unroll
    for (int nt = 0; nt < 16; nt++)
#pragma unroll
        for (int j = 0; j < 4; j++) cacc[nt][j] = 0.f;

#pragma unroll 1
    for (int ic = 0; ic < 4; ic++) {
        const uint32_t buf = sb + (uint32_t)(ic & 1) * PJ_BUF;
        if (ic < 3) {
            pj_prefetch(sb + (uint32_t)((ic + 1) & 1) * PJ_BUF, xh, xl, wh, wl,
                        (ic + 1) * 64, tid);
            CP_COMMIT();
            CP_WAIT(1);
        } else {
            CP_WAIT(0);
        }
        __syncthreads();

#pragma unroll
        for (int ks = 0; ks < 4; ks++) {
            int cb = ks * 16;
            uint32_t ah0, ah1, ah2, ah3, al0, al1, al2, al3;
            uint32_t aaddr = (Rbase + a_row) * 144 + (cb + a_col) * 2;
            ldsm_x4(ah0, ah1, ah2, ah3, buf + PJ_AH + aaddr);
            ldsm_x4(al0, al1, al2, al3, buf + PJ_AL + aaddr);
#pragma unroll
            for (int n2 = 0; n2 < 8; n2++) {
                uint32_t bh0, bh1, bh2, bh3, bl0, bl1, bl2, bl3;
                uint32_t baddr = (n2 * 16 + b4_row) * 144 + (cb + b4_col) * 2;
                ldsm_x4(bh0, bh1, bh2, bh3, buf + PJ_BH + baddr);
                ldsm_x4(bl0, bl1, bl2, bl3, buf + PJ_BL + baddr);
                mma_bf16(cacc[2*n2],   ah0, ah1, ah2, ah3, bh0, bh1);
                mma_bf16(cacc[2*n2],   ah0, ah1, ah2, ah3, bl0, bl1);
                mma_bf16(cacc[2*n2],   al0, al1, al2, al3, bh0, bh1);
                mma_bf16(cacc[2*n2+1], ah0, ah1, ah2, ah3, bh2, bh3);
                mma_bf16(cacc[2*n2+1], ah0, ah1, ah2, ah3, bl2, bl3);
                mma_bf16(cacc[2*n2+1], al0, al1, al2, al3, bh2, bh3);
            }
        }
        __syncthreads();
    }

    // ---- epilogue ----
    if (z == 0) {
        int p0 = Rbase + (lane >> 2);
        int p1 = p0 + 8;
        int g0 = p0 >> 2, s0 = p0 & 3;
        int g1 = p1 >> 2, s1 = p1 & 3;
        int n0 = (2 * r + (s0 >> 1)) * WWID + ((g0 << 1) | (s0 & 1));
        int n1 = (2 * r + (s1 >> 1)) * WWID + ((g1 << 1) | (s1 & 1));
        size_t b0 = ((size_t)(b * NN + n0)) * CI;
        size_t b1 = ((size_t)(b * NN + n1)) * CI;
#pragma unroll
        for (int nt = 0; nt < 16; nt++) {
            int ci = nt * 8 + 2 * (lane & 3);
            float bi0 = bias[ci], bi1 = bias[ci + 1];
            uint32_t h, l;
            split2(cacc[nt][0] + bi0, cacc[nt][1] + bi1, h, l);
            *(uint32_t*)(d_thh + b0 + ci) = h;
            *(uint32_t*)(d_thl + b0 + ci) = l;
            split2(cacc[nt][2] + bi0, cacc[nt][3] + bi1, h, l);
            *(uint32_t*)(d_thh + b1 + ci) = h;
            *(uint32_t*)(d_thl + b1 + ci) = l;
        }
    } else {
        int k01 = r * 32 + wid * 4 + (lane >> 4);
        int k23 = k01 + 2;
        bool writer = ((lane >> 2) & 3) == 0;
#pragma unroll
        for (int nt = 0; nt < 16; nt++) {
            int ci = nt * 8 + 2 * (lane & 3);
            float m01a = qmax(cacc[nt][0]);
            float m01b = qmax(cacc[nt][1]);
            float m23a = qmax(cacc[nt][2]);
            float m23b = qmax(cacc[nt][3]);
            if (writer) {
                float bi0 = bias[ci], bi1 = bias[ci + 1];
                float v01a = m01a + bi0, v01b = m01b + bi1;
                float v23a = m23a + bi0, v23b = m23b + bi1;
                if (z == 1) {
                    uint32_t h, l;
                    split2(v01a, v01b, h, l);
                    *(uint32_t*)(d_phh + ((size_t)(b * NK + k01)) * CI + ci) = h;
                    *(uint32_t*)(d_phl + ((size_t)(b * NK + k01)) * CI + ci) = l;
                    split2(v23a, v23b, h, l);
                    *(uint32_t*)(d_phh + ((size_t)(b * NK + k23)) * CI + ci) = h;
                    *(uint32_t*)(d_phl + ((size_t)(b * NK + k23)) * CI + ci) = l;
                } else {
                    size_t gb = (size_t)b * CI * NK;
                    float h01a = __bfloat162float(__float2bfloat16(v01a));
                    float h01b = __bfloat162float(__float2bfloat16(v01b));
                    float h23a = __bfloat162float(__float2bfloat16(v23a));
                    float h23b = __bfloat162float(__float2bfloat16(v23b));
                    d_gh[gb + (size_t)ci * NK + k01]       = __float2bfloat16(v01a);
                    d_gh[gb + (size_t)(ci + 1) * NK + k01] = __float2bfloat16(v01b);
                    d_gh[gb + (size_t)ci * NK + k23]       = __float2bfloat16(v23a);
                    d_gh[gb + (size_t)(ci + 1) * NK + k23] = __float2bfloat16(v23b);
                    d_gl[gb + (size_t)ci * NK + k01]       = __float2bfloat16(v01a - h01a);
                    d_gl[gb + (size_t)(ci + 1) * NK + k01] = __float2bfloat16(v01b - h01b);
                    d_gl[gb + (size_t)ci * NK + k23]       = __float2bfloat16(v23a - h23a);
                    d_gl[gb + (size_t)(ci + 1) * NK + k23] = __float2bfloat16(v23b - h23b);
                }
            }
        }
    }
}

// =====================================================================
// Kernel 2: warp-MMA bf16 split flash attention (unchanged, passing).
// =====================================================================
#define SM_QH 0
#define SM_QL 34816
#define SM_BUF 69632
#define BUF_SZ 71680
#define BUF_KH 0
#define BUF_KL 17408
#define BUF_GH 34816
#define BUF_GL 53248
#define ATTN_SMEM_BYTES (SM_BUF + 2 * BUF_SZ)   // 212,992

__device__ __forceinline__ void prefetch_chunk(uint32_t bufb, int b, int c0, int tid)
{
    const __nv_bfloat16* kh = d_phh + (size_t)(b * NK + c0) * CI;
    const __nv_bfloat16* kl = d_phl + (size_t)(b * NK + c0) * CI;
    const __nv_bfloat16* gh = d_gh + (size_t)b * CI * NK + c0;
    const __nv_bfloat16* gl = d_gl + (size_t)b * CI * NK + c0;
#pragma unroll
    for (int it = 0; it < 4; it++) {
        int idx = it * 256 + tid;
        int krow = idx >> 4, c8 = (idx & 15) * 8;
        cp_async16(bufb + BUF_KH + krow * 272 + c8 * 2, kh + (size_t)krow * CI + c8);
        cp_async16(bufb + BUF_KL + krow * 272 + c8 * 2, kl + (size_t)krow * CI + c8);
        int drow = idx >> 3, k8 = (idx & 7) * 8;
        cp_async16(bufb + BUF_GH + drow * 144 + k8 * 2, gh + (size_t)drow * NK + k8);
        cp_async16(bufb + BUF_GL + drow * 144 + k8 * 2, gl + (size_t)drow * NK + k8);
    }
}

__global__ __launch_bounds__(256, 1)
void attn_kernel()
{
    extern __shared__ char smc[];
    const uint32_t sb = smem_u32(smc);
    const int tid  = threadIdx.x;
    const int wid  = tid >> 5;
    const int lane = tid & 31;
    const int b    = blockIdx.y;
    const int q0   = blockIdx.x * 128;

    prefetch_chunk(sb + SM_BUF, b, 0, tid);
    CP_COMMIT();

    {
        const __nv_bfloat16* qh = d_thh + (size_t)(b * NN + q0) * CI;
        const __nv_bfloat16* ql = d_thl + (size_t)(b * NN + q0) * CI;
#pragma unroll
        for (int it = 0; it < 8; it++) {
            int idx = it * 256 + tid;
            int row = idx >> 4, c8 = (idx & 15) * 8;
            *(uint4*)(smc + SM_QH + row * 272 + c8 * 2) =
                *(const uint4*)(qh + (size_t)row * CI + c8);
            *(uint4*)(smc + SM_QL + row * 272 + c8 * 2) =
                *(const uint4*)(ql + (size_t)row * CI + c8);
        }
    }

    const int a_row = (lane & 7) + 8 * ((lane >> 3) & 1);
    const int a_col = 8 * (lane >> 4);
    const int b4_row = 8 * (lane >> 4) + (lane & 7);
    const int b4_col = 8 * ((lane >> 3) & 1);
    const int Rbase = wid * 16;

    float yacc[16][4];
#pragma unroll
    for (int dt = 0; dt < 16; dt++)
#pragma unroll
        for (int j = 0; j < 4; j++) yacc[dt][j] = 0.f;
    float m0 = -1e30f, m1 = -1e30f, l0 = 0.f, l1 = 0.f;

#pragma unroll 1
    for (int ic = 0; ic < 16; ic++) {
        const uint32_t cb_buf = sb + SM_BUF + (uint32_t)(ic & 1) * BUF_SZ;

        if (ic < 15) {
            prefetch_chunk(sb + SM_BUF + (uint32_t)((ic + 1) & 1) * BUF_SZ,
                           b, (ic + 1) * 64, tid);
            CP_COMMIT();
            CP_WAIT(1);
        } else {
            CP_WAIT(0);
        }
        __syncthreads();

        float sacc[8][4];
#pragma unroll
        for (int n = 0; n < 8; n++)
#pragma unroll
            for (int j = 0; j < 4; j++) sacc[n][j] = 0.f;

#pragma unroll
        for (int m = 0; m < 8; m++) {
            int cb = m * 16;
            uint32_t ah0, ah1, ah2, ah3, al0, al1, al2, al3;
            ldsm_x4(ah0, ah1, ah2, ah3,
                    sb + SM_QH + (Rbase + a_row) * 272 + (cb + a_col) * 2);
            ldsm_x4(al0, al1, al2, al3,
                    sb + SM_QL + (Rbase + a_row) * 272 + (cb + a_col) * 2);
#pragma unroll
            for (int n2 = 0; n2 < 4; n2++) {
                uint32_t kh0, kh1, kh2, kh3, kl0, kl1, kl2, kl3;
                uint32_t kaddr = (n2 * 16 + b4_row) * 272 + (cb + b4_col) * 2;
                ldsm_x4(kh0, kh1, kh2, kh3, cb_buf + BUF_KH + kaddr);
                ldsm_x4(kl0, kl1, kl2, kl3, cb_buf + BUF_KL + kaddr);
                mma_bf16(sacc[2*n2],   ah0, ah1, ah2, ah3, kh0, kh1);
                mma_bf16(sacc[2*n2],   ah0, ah1, ah2, ah3, kl0, kl1);
                mma_bf16(sacc[2*n2],   al0, al1, al2, al3, kh0, kh1);
                mma_bf16(sacc[2*n2+1], ah0, ah1, ah2, ah3, kh2, kh3);
                mma_bf16(sacc[2*n2+1], ah0, ah1, ah2, ah3, kl2, kl3);
                mma_bf16(sacc[2*n2+1], al0, al1, al2, al3, kh2, kh3);
            }
        }

        float mc0 = -1e30f, mc1 = -1e30f;
#pragma unroll
        for (int n = 0; n < 8; n++) {
            mc0 = fmaxf(mc0, fmaxf(sacc[n][0], sacc[n][1]));
            mc1 = fmaxf(mc1, fmaxf(sacc[n][2], sacc[n][3]));
        }
        mc0 = fmaxf(mc0, __shfl_xor_sync(0xffffffffu, mc0, 1));
        mc0 = fmaxf(mc0, __shfl_xor_sync(0xffffffffu, mc0, 2));
        mc1 = fmaxf(mc1, __shfl_xor_sync(0xffffffffu, mc1, 1));
        mc1 = fmaxf(mc1, __shfl_xor_sync(0xffffffffu, mc1, 2));
        float mn0 = fmaxf(m0, mc0), mn1 = fmaxf(m1, mc1);
        float sc0 = __expf(m0 - mn0), sc1 = __expf(m1 - mn1);
        m0 = mn0; m1 = mn1;
        l0 *= sc0; l1 *= sc1;
#pragma unroll
        for (int dt = 0; dt < 16; dt++) {
            yacc[dt][0] *= sc0; yacc[dt][1] *= sc0;
            yacc[dt][2] *= sc1; yacc[dt][3] *= sc1;
        }

        uint32_t pa_h[4][4], pa_l[4][4];
#pragma unroll
        for (int n = 0; n < 8; n++) {
            float p0 = __expf(sacc[n][0] - mn0);
            float p1 = __expf(sacc[n][1] - mn0);
            float p2 = __expf(sacc[n][2] - mn1);
            float p3 = __expf(sacc[n][3] - mn1);
            l0 += p0 + p1;
            l1 += p2 + p3;
            float h0 = __bfloat162float(__float2bfloat16(p0));
            float h1 = __bfloat162float(__float2bfloat16(p1));
            float h2 = __bfloat162float(__float2bfloat16(p2));
            float h3 = __bfloat162float(__float2bfloat16(p3));
            uint32_t h01, h23, lo01, lo23;
            CVT_BF16X2(h01, p0, p1);
            CVT_BF16X2(h23, p2, p3);
            CVT_BF16X2(lo01, p0 - h0, p1 - h1);
            CVT_BF16X2(lo23, p2 - h2, p3 - h3);
            int m2 = n >> 1;
            if ((n & 1) == 0) {
                pa_h[m2][0] = h01;  pa_h[m2][1] = h23;
                pa_l[m2][0] = lo01; pa_l[m2][1] = lo23;
            } else {
                pa_h[m2][2] = h01;  pa_h[m2][3] = h23;
                pa_l[m2][2] = lo01; pa_l[m2][3] = lo23;
            }
        }

#pragma unroll
        for (int m2 = 0; m2 < 4; m2++) {
            int kb = m2 * 16;
#pragma unroll
            for (int dt2 = 0; dt2 < 8; dt2++) {
                uint32_t gh0, gh1, gh2, gh3, gl0, gl1, gl2, gl3;
                uint32_t gaddr = (dt2 * 16 + b4_row) * 144 + (kb + b4_col) * 2;
                ldsm_x4(gh0, gh1, gh2, gh3, cb_buf + BUF_GH + gaddr);
                ldsm_x4(gl0, gl1, gl2, gl3, cb_buf + BUF_GL + gaddr);
                mma_bf16(yacc[2*dt2],   pa_h[m2][0], pa_h[m2][1], pa_h[m2][2], pa_h[m2][3], gh0, gh1);
                mma_bf16(yacc[2*dt2],   pa_l[m2][0], pa_l[m2][1], pa_l[m2][2], pa_l[m2][3], gh0, gh1);
                mma_bf16(yacc[2*dt2],   pa_h[m2][0], pa_h[m2][1], pa_h[m2][2], pa_h[m2][3], gl0, gl1);
                mma_bf16(yacc[2*dt2+1], pa_h[m2][0], pa_h[m2][1], pa_h[m2][2], pa_h[m2][3], gh2, gh3);
                mma_bf16(yacc[2*dt2+1], pa_l[m2][0], pa_l[m2][1], pa_l[m2][2], pa_l[m2][3], gh2, gh3);
                mma_bf16(yacc[2*dt2+1], pa_h[m2][0], pa_h[m2][1], pa_h[m2][2], pa_h[m2][3], gl2, gl3);
            }
        }
        __syncthreads();
    }

    l0 += __shfl_xor_sync(0xffffffffu, l0, 1);
    l0 += __shfl_xor_sync(0xffffffffu, l0, 2);
    l1 += __shfl_xor_sync(0xffffffffu, l1, 1);
    l1 += __shfl_xor_sync(0xffffffffu, l1, 2);
    float inv0 = 1.f / l0, inv1 = 1.f / l1;

    int r0 = lane >> 2;
    int cofs = (lane & 3) * 2;
    float* dst0 = d_y + ((size_t)(b * NN + q0 + Rbase + r0)) * CI;
    float* dst1 = d_y + ((size_t)(b * NN + q0 + Rbase + r0 + 8)) * CI;
#pragma unroll
    for (int dt = 0; dt < 16; dt++) {
        *(float2*)&dst0[dt * 8 + cofs] = make_float2(yacc[dt][0] * inv0, yacc[dt][1] * inv0);
        *(float2*)&dst1[dt * 8 + cofs] = make_float2(yacc[dt][2] * inv1, yacc[dt][3] * inv1);
    }
}

// =====================================================================
// Kernel 3: z = BN(conv1x1(y, W)) + fuse -> concat band 1 (unchanged).
// =====================================================================
__global__ __launch_bounds__(256, 2)
void wz_kernel(const float* __restrict__ fuse,
               const float* __restrict__ W_b,
               const float* __restrict__ gamma, const float* __restrict__ beta,
               const float* __restrict__ mean,  const float* __restrict__ var,
               float* __restrict__ out)
{
    __shared__ __align__(16) float ys[32 * 132];
    __shared__ __align__(16) float wsm[32 * 132];

    const int b  = blockIdx.z;
    const int c0 = blockIdx.y * 128;
    const int n0 = blockIdx.x * 128;
    const int tid = threadIdx.x;
    const int ty = tid >> 4;
    const int tx = tid & 15;

    u64 acc2[8][4];
#pragma unroll
    for (int i = 0; i < 8; i++)
#pragma unroll
        for (int j = 0; j < 4; j++) acc2[i][j] = 0ull;

    for (int k0 = 0; k0 < CI; k0 += 32) {
        __syncthreads();
#pragma unroll
        for (int p = 0; p < 4; p++) {
            int idx = p * 256 + tid;
            int n = idx >> 3, c4 = idx & 7;
            float4 v = *(const float4*)&d_y[((size_t)b * NN + n0 + n) * CI + k0 + c4 * 4];
            ys[(c4 * 4 + 0) * 132 + n] = v.x;
            ys[(c4 * 4 + 1) * 132 + n] = v.y;
            ys[(c4 * 4 + 2) * 132 + n] = v.z;
            ys[(c4 * 4 + 3) * 132 + n] = v.w;
            int ci = idx >> 5, g4 = idx & 31;
            *(float4*)&wsm[ci * 132 + g4 * 4] =
                *(const float4*)&d_wT[(size_t)(k0 + ci) * CC + c0 + g4 * 4];
        }
        __syncthreads();
#pragma unroll
        for (int cc = 0; cc < 32; cc++) {
            float4 wlo = *(const float4*)&wsm[cc * 132 + ty * 4];
            float4 whi = *(const float4*)&wsm[cc * 132 + 64 + ty * 4];
            float4 ylo = *(const float4*)&ys[cc * 132 + tx * 4];
            float4 yhi = *(const float4*)&ys[cc * 132 + 64 + tx * 4];
            u64 yp[4] = {pk2(ylo.x, ylo.y), pk2(ylo.z, ylo.w),
                         pk2(yhi.x, yhi.y), pk2(yhi.z, yhi.w)};
            const float wv[8] = {wlo.x, wlo.y, wlo.z, wlo.w,
                                 whi.x, whi.y, whi.z, whi.w};
#pragma unroll
            for (int i = 0; i < 8; i++) {
                u64 wd = dup2(wv[i]);
#pragma unroll
                for (int j = 0; j < 4; j++) fma2(acc2[i][j], wd, yp[j]);
            }
        }
    }

#pragma unroll
    for (int i = 0; i < 8; i++) {
        int c = c0 + ((i < 4) ? (ty * 4 + i) : (64 + ty * 4 + i - 4));
        float inv = gamma[c] * rsqrtf(var[c] + 1e-5f);
        float be  = (W_b[c] - mean[c]) * inv + beta[c];
        float a[8];
        up2(a[0], a[1], acc2[i][0]); up2(a[2], a[3], acc2[i][1]);
        up2(a[4], a[5], acc2[i][2]); up2(a[6], a[7], acc2[i][3]);
        const float* fr = &fuse[((size_t)b * CC + c) * NN + n0];
        float* orow = &out[((size_t)b * 768 + 256 + c) * NN + n0];
        float4 f0 = *(const float4*)&fr[tx * 4];
        float4 f1 = *(const float4*)&fr[64 + tx * 4];
        *(float4*)&orow[tx * 4] = make_float4(a[0]*inv + be + f0.x, a[1]*inv + be + f0.y,
                                              a[2]*inv + be + f0.z, a[3]*inv + be + f0.w);
        *(float4*)&orow[64 + tx * 4] = make_float4(a[4]*inv + be + f1.x, a[5]*inv + be + f1.y,
                                                   a[6]*inv + be + f1.z, a[7]*inv + be + f1.w);
    }
}

// =====================================================================
extern "C" void kernel_launch(void* const* d_in, const int* in_sizes, int n_in,
                              void* d_out, int out_size)
{
    const float* lc      = (const float*)d_in[0];
    const float* fuse    = (const float*)d_in[1];
    const float* gc      = (const float*)d_in[2];
    const float* g_w     = (const float*)d_in[3];
    const float* g_b     = (const float*)d_in[4];
    const float* theta_w = (const float*)d_in[5];
    const float* theta_b = (const float*)d_in[6];
    const float* phi_w   = (const float*)d_in[7];
    const float* phi_b   = (const float*)d_in[8];
    const float* W_w     = (const float*)d_in[9];
    const float* W_b     = (const float*)d_in[10];
    const float* bn_g    = (const float*)d_in[11];
    const float* bn_b    = (const float*)d_in[12];
    const float* bn_m    = (const float*)d_in[13];
    const float* bn_v    = (const float*)d_in[14];
    float* out = (float*)d_out;

    (void)in_sizes; (void)n_in; (void)out_size;

    cudaFuncSetAttribute(attn_kernel, cudaFuncAttributeMaxDynamicSharedMemorySize,
                         ATTN_SMEM_BYTES);
    cudaFuncSetAttribute(proj_mma_kernel, cudaFuncAttributeMaxDynamicSharedMemorySize,
                         PROJ_SMEM_BYTES);

    wt_kernel<<<32, 256>>>(W_w);
    wsplit_kernel<<<96, 256>>>(theta_w, phi_w, g_w);
    splitx_kernel<<<dim3(32, 4, BB), 256>>>(fuse);

    // dedicated high-MLP band copy (was serialized inside proj_mma: 1.4 TB/s)
    copy_kernel<<<8192, 256>>>((const float4*)lc, (const float4*)gc, (float4*)out);

    proj_mma_kernel<<<dim3(32, BB, 3), 256, PROJ_SMEM_BYTES>>>(g_b, theta_b, phi_b);

    attn_kernel<<<dim3(NN / 128, BB), 256, ATTN_SMEM_BYTES>>>();

    wz_kernel<<<dim3(NN / 128, CC / 128, BB), 256>>>(
        fuse, W_b, bn_g, bn_b, bn_m, bn_v, out);
}